// round 3
// baseline (speedup 1.0000x reference)
#include <cuda_runtime.h>
#include <math.h>

#define S_DIM 128
#define R_DIM 256
#define C_DIM 256
#define H_DIM 8
#define D_DIM 32
#define HD_DIM 256
#define SR_DIM (S_DIM * R_DIM)

// Scratch (device globals; allocation-free contract)
__device__ float g_Q[S_DIM * H_DIM * R_DIM * D_DIM];   // [s][h][r][d]
__device__ float g_K[S_DIM * H_DIM * R_DIM * D_DIM];
__device__ float g_V[S_DIM * H_DIM * R_DIM * D_DIM];
__device__ float g_G[S_DIM * H_DIM * R_DIM * D_DIM];
__device__ float g_O[S_DIM * H_DIM * R_DIM * D_DIM];
__device__ float g_biasT[H_DIM * R_DIM * R_DIM];       // [h][q][k]

// ---------------------------------------------------------------------------
// Kernel 1: bias [q][k][h] -> biasT [h][q][k]  (makes per-query bias reads
// contiguous in k; bias is s-independent and L2-resident thereafter)
// ---------------------------------------------------------------------------
__global__ void bias_transpose_kernel(const float* __restrict__ bias) {
    int idx = blockIdx.x * blockDim.x + threadIdx.x;
    if (idx < H_DIM * R_DIM * R_DIM) {
        int k  = idx & 255;
        int qq = (idx >> 8) & 255;
        int h  = idx >> 16;
        g_biasT[idx] = bias[((qq << 8) + k) * 8 + h];
    }
}

// ---------------------------------------------------------------------------
// Kernel 2: fused projections. type z: 0=Q(*norm) 1=K 2=V 3=G(sigmoid+b_g)
// C = A[SR,256] * W[256,256], 128x128 tile, k-chunk 8, 8x8 per thread.
// Output layout [s][h][r][d].
// ---------------------------------------------------------------------------
__global__ void proj_kernel(const float* __restrict__ qin,
                            const float* __restrict__ kvin,
                            const float* __restrict__ w_q,
                            const float* __restrict__ w_k,
                            const float* __restrict__ w_v,
                            const float* __restrict__ w_g,
                            const float* __restrict__ b_g) {
    __shared__ float As[8][128];
    __shared__ float Bs[8][128];
    int type = blockIdx.z;
    const float* A = (type == 1 || type == 2) ? kvin : qin;
    const float* W = (type == 0) ? w_q : (type == 1) ? w_k : (type == 2) ? w_v : w_g;
    float* Out = (type == 0) ? g_Q : (type == 1) ? g_K : (type == 2) ? g_V : g_G;

    int t = threadIdx.x;
    int bM = blockIdx.x * 128;
    int bN = blockIdx.y * 128;
    int tx = t & 15, ty = t >> 4;
    int arow = t >> 1, ak = (t & 1) * 4;
    int bk = t >> 5, bcol = (t & 31) * 4;

    float acc[8][8];
#pragma unroll
    for (int i = 0; i < 8; i++)
#pragma unroll
        for (int j = 0; j < 8; j++) acc[i][j] = 0.f;

    for (int k0 = 0; k0 < 256; k0 += 8) {
        float4 av = *(const float4*)&A[(bM + arow) * 256 + k0 + ak];
        float4 bv = *(const float4*)&W[(k0 + bk) * 256 + bN + bcol];
        __syncthreads();
        As[ak + 0][arow] = av.x;
        As[ak + 1][arow] = av.y;
        As[ak + 2][arow] = av.z;
        As[ak + 3][arow] = av.w;
        *(float4*)&Bs[bk][bcol] = bv;
        __syncthreads();
#pragma unroll
        for (int kk = 0; kk < 8; kk++) {
            float4 a0 = *(const float4*)&As[kk][ty * 8];
            float4 a1 = *(const float4*)&As[kk][ty * 8 + 4];
            float4 b0 = *(const float4*)&Bs[kk][tx * 8];
            float4 b1 = *(const float4*)&Bs[kk][tx * 8 + 4];
            float a[8] = {a0.x, a0.y, a0.z, a0.w, a1.x, a1.y, a1.z, a1.w};
            float b[8] = {b0.x, b0.y, b0.z, b0.w, b1.x, b1.y, b1.z, b1.w};
#pragma unroll
            for (int i = 0; i < 8; i++)
#pragma unroll
                for (int j = 0; j < 8; j++) acc[i][j] += a[i] * b[j];
        }
    }

#pragma unroll
    for (int i = 0; i < 8; i++) {
        int row = bM + ty * 8 + i;
        int s = row >> 8, r = row & 255;
#pragma unroll
        for (int j = 0; j < 8; j++) {
            int col = bN + tx * 8 + j;
            int h = col >> 5, d = col & 31;
            float v = acc[i][j];
            if (type == 0) v *= 0.17677669529663687f;  // 1/sqrt(32)
            if (type == 3) v = 1.f / (1.f + __expf(-(v + b_g[col])));
            Out[((s * 8 + h) * 256 + r) * 32 + d] = v;
        }
    }
}

// ---------------------------------------------------------------------------
// Kernel 3: attention per (s, h). 256 threads = 256 queries. K/V resident in
// SMEM; bias staged per 32-key chunk in padded SMEM. Fixed-reference softmax
// (scores bounded; mask -1e9 underflows exp to 0 exactly).
// ---------------------------------------------------------------------------
__global__ void attn_kernel(const float* __restrict__ bias_mask) {
    extern __shared__ float sm[];
    float* Ks = sm;                          // 256*32
    float* Vs = sm + 8192;                   // 256*32
    float* Bb = sm + 16384;                  // 256*33 (padded)
    float* Mb = sm + 16384 + 256 * 33;       // 256

    int s = blockIdx.x, h = blockIdx.y;
    int t = threadIdx.x;

    const float4* Kg = (const float4*)(g_K + (s * 8 + h) * R_DIM * D_DIM);
    const float4* Vg = (const float4*)(g_V + (s * 8 + h) * R_DIM * D_DIM);
#pragma unroll
    for (int i = t; i < 2048; i += 256) {
        ((float4*)Ks)[i] = Kg[i];
        ((float4*)Vs)[i] = Vg[i];
    }
    Mb[t] = (bias_mask[s * 256 + t] - 1.f) * 1e9f;

    float qreg[32];
    const float4* Qg = (const float4*)(g_Q + ((s * 8 + h) * R_DIM + t) * D_DIM);
#pragma unroll
    for (int i = 0; i < 8; i++) {
        float4 v = Qg[i];
        qreg[i * 4 + 0] = v.x; qreg[i * 4 + 1] = v.y;
        qreg[i * 4 + 2] = v.z; qreg[i * 4 + 3] = v.w;
    }

    float l = 0.f;
    float acc[32];
#pragma unroll
    for (int d = 0; d < 32; d++) acc[d] = 0.f;

    const float* biasBase = g_biasT + (h * 256) * 256;

    for (int kc = 0; kc < 256; kc += 32) {
        __syncthreads();
        // stage bias chunk [256 q][32 k] -> Bb[q*33 + k] (conflict-free)
        for (int f = t; f < 2048; f += 256) {
            int qq = f >> 3, k4 = (f & 7) * 4;
            float4 v = *(const float4*)&biasBase[qq * 256 + kc + k4];
            Bb[qq * 33 + k4 + 0] = v.x;
            Bb[qq * 33 + k4 + 1] = v.y;
            Bb[qq * 33 + k4 + 2] = v.z;
            Bb[qq * 33 + k4 + 3] = v.w;
        }
        __syncthreads();
#pragma unroll 4
        for (int kk = 0; kk < 32; kk++) {
            int k = kc + kk;
            const float* Kr = Ks + k * 32;
            float s0 = 0.f, s1 = 0.f, s2 = 0.f, s3 = 0.f;
#pragma unroll
            for (int d = 0; d < 32; d += 4) {
                s0 += qreg[d + 0] * Kr[d + 0];
                s1 += qreg[d + 1] * Kr[d + 1];
                s2 += qreg[d + 2] * Kr[d + 2];
                s3 += qreg[d + 3] * Kr[d + 3];
            }
            float sc = Bb[t * 33 + kk] + Mb[k] + ((s0 + s1) + (s2 + s3));
            float p = __expf(sc);
            l += p;
            const float* Vr = Vs + k * 32;
#pragma unroll
            for (int d = 0; d < 32; d++) acc[d] += p * Vr[d];
        }
    }

    float inv = 1.f / l;
    float* Og = g_O + ((s * 8 + h) * R_DIM + t) * D_DIM;
#pragma unroll
    for (int d = 0; d < 32; d++) Og[d] = acc[d] * inv;
}

// ---------------------------------------------------------------------------
// Kernel 4: out[sr,c] = sum_hd (O*G)[sr,hd] * Wo[hd,c] + b_o[c]
// Same 128x128 SGEMM; A tile formed as O*G on the fly.
// ---------------------------------------------------------------------------
__global__ void outproj_kernel(const float* __restrict__ w_o,
                               const float* __restrict__ b_o,
                               float* __restrict__ out) {
    __shared__ float As[8][128];
    __shared__ float Bs[8][128];
    int t = threadIdx.x;
    int bM = blockIdx.x * 128;
    int bN = blockIdx.y * 128;
    int tx = t & 15, ty = t >> 4;
    int arow = t >> 1, ak = (t & 1) * 4;
    int bk = t >> 5, bcol = (t & 31) * 4;

    float acc[8][8];
#pragma unroll
    for (int i = 0; i < 8; i++)
#pragma unroll
        for (int j = 0; j < 8; j++) acc[i][j] = 0.f;

    int row = bM + arow;
    int s = row >> 8, r = row & 255;

    for (int k0 = 0; k0 < 256; k0 += 8) {
        int hh = k0 >> 5;
        int d0 = (k0 & 31) + ak;  // multiple of 4
        int base = (((s * 8 + hh) * 256 + r) * 32 + d0) >> 2;
        float4 ov = ((const float4*)g_O)[base];
        float4 gv = ((const float4*)g_G)[base];
        float4 av;
        av.x = ov.x * gv.x; av.y = ov.y * gv.y;
        av.z = ov.z * gv.z; av.w = ov.w * gv.w;
        float4 bv = *(const float4*)&w_o[(k0 + bk) * 256 + bN + bcol];
        __syncthreads();
        As[ak + 0][arow] = av.x;
        As[ak + 1][arow] = av.y;
        As[ak + 2][arow] = av.z;
        As[ak + 3][arow] = av.w;
        *(float4*)&Bs[bk][bcol] = bv;
        __syncthreads();
#pragma unroll
        for (int kk = 0; kk < 8; kk++) {
            float4 a0 = *(const float4*)&As[kk][ty * 8];
            float4 a1 = *(const float4*)&As[kk][ty * 8 + 4];
            float4 b0 = *(const float4*)&Bs[kk][tx * 8];
            float4 b1 = *(const float4*)&Bs[kk][tx * 8 + 4];
            float a[8] = {a0.x, a0.y, a0.z, a0.w, a1.x, a1.y, a1.z, a1.w};
            float b[8] = {b0.x, b0.y, b0.z, b0.w, b1.x, b1.y, b1.z, b1.w};
#pragma unroll
            for (int i = 0; i < 8; i++)
#pragma unroll
                for (int j = 0; j < 8; j++) acc[i][j] += a[i] * b[j];
        }
    }

#pragma unroll
    for (int i = 0; i < 8; i++) {
        int orow = bM + ty * 8 + i;
#pragma unroll
        for (int j = 0; j < 8; j++) {
            int col = bN + tx * 8 + j;
            out[orow * 256 + col] = acc[i][j] + b_o[col];
        }
    }
}

// ---------------------------------------------------------------------------
extern "C" void kernel_launch(void* const* d_in, const int* in_sizes, int n_in,
                              void* d_out, int out_size) {
    const float* q    = (const float*)d_in[0];
    const float* kv   = (const float*)d_in[1];
    const float* bias = (const float*)d_in[2];
    const float* mask = (const float*)d_in[3];
    const float* w_q  = (const float*)d_in[4];
    const float* w_k  = (const float*)d_in[5];
    const float* w_v  = (const float*)d_in[6];
    const float* w_g  = (const float*)d_in[7];
    const float* b_g  = (const float*)d_in[8];
    const float* w_o  = (const float*)d_in[9];
    const float* b_o  = (const float*)d_in[10];
    float* out = (float*)d_out;

    bias_transpose_kernel<<<(H_DIM * R_DIM * R_DIM + 255) / 256, 256>>>(bias);

    proj_kernel<<<dim3(SR_DIM / 128, HD_DIM / 128, 4), 256>>>(
        q, kv, w_q, w_k, w_v, w_g, b_g);

    const int ATTN_SMEM = (8192 + 8192 + 256 * 33 + 256) * 4;  // 100352 B
    cudaFuncSetAttribute(attn_kernel,
                         cudaFuncAttributeMaxDynamicSharedMemorySize, ATTN_SMEM);
    attn_kernel<<<dim3(S_DIM, H_DIM), 256, ATTN_SMEM>>>(mask);

    outproj_kernel<<<dim3(SR_DIM / 128, C_DIM / 128), 256>>>(w_o, b_o, out);
}

// round 4
// speedup vs baseline: 1.5840x; 1.5840x over previous
#include <cuda_runtime.h>
#include <math.h>
#include <stdint.h>

#define S_DIM 128
#define R_DIM 256
#define C_DIM 256
#define H_DIM 8
#define D_DIM 32
#define HD_DIM 256
#define SR_DIM (S_DIM * R_DIM)

// Scratch (device globals; allocation-free contract)
__device__ float g_Q[S_DIM * H_DIM * R_DIM * D_DIM];   // [s][h][r][d]
__device__ float g_K[S_DIM * H_DIM * R_DIM * D_DIM];
__device__ float g_V[S_DIM * H_DIM * R_DIM * D_DIM];
__device__ float g_G[S_DIM * H_DIM * R_DIM * D_DIM];
__device__ float g_O[S_DIM * H_DIM * R_DIM * D_DIM];
__device__ float g_biasT[H_DIM * R_DIM * R_DIM];       // [h][q][k]

// ---------------------------------------------------------------------------
// TF32 helpers
// ---------------------------------------------------------------------------
__device__ __forceinline__ uint32_t f2tf(float f) {
    uint32_t u;
    asm("cvt.rna.tf32.f32 %0, %1;" : "=r"(u) : "f"(f));
    return u;
}

__device__ __forceinline__ void mma_tf32(float c[4],
                                         uint32_t a0, uint32_t a1,
                                         uint32_t a2, uint32_t a3,
                                         uint32_t b0, uint32_t b1) {
    asm volatile(
        "mma.sync.aligned.m16n8k8.row.col.f32.tf32.tf32.f32 "
        "{%0,%1,%2,%3}, {%4,%5,%6,%7}, {%8,%9}, {%0,%1,%2,%3};"
        : "+f"(c[0]), "+f"(c[1]), "+f"(c[2]), "+f"(c[3])
        : "r"(a0), "r"(a1), "r"(a2), "r"(a3), "r"(b0), "r"(b1));
}

// ---------------------------------------------------------------------------
// Kernel 1: bias [q][k][h] -> biasT [h][q][k]
// ---------------------------------------------------------------------------
__global__ void bias_transpose_kernel(const float* __restrict__ bias) {
    int idx = blockIdx.x * blockDim.x + threadIdx.x;
    if (idx < H_DIM * R_DIM * R_DIM) {
        int k  = idx & 255;
        int qq = (idx >> 8) & 255;
        int h  = idx >> 16;
        g_biasT[idx] = bias[((qq << 8) + k) * 8 + h];
    }
}

// ---------------------------------------------------------------------------
// Kernel 2: fused projections via tf32 mma.sync.
// C[M=32768, N=256] = A[M,256] * W[256,256]; type z: 0=Q(*norm) 1=K 2=V
// 3=G(sigmoid+b_g). Block 128x128, BK=32, 8 warps of 64x32 warp tiles.
// ---------------------------------------------------------------------------
__global__ void __launch_bounds__(256)
proj_mma_kernel(const float* __restrict__ qin,
                const float* __restrict__ kvin,
                const float* __restrict__ w_q,
                const float* __restrict__ w_k,
                const float* __restrict__ w_v,
                const float* __restrict__ w_g,
                const float* __restrict__ b_g) {
    __shared__ uint32_t As[128][36];   // padded: frag reads conflict-free
    __shared__ uint32_t Bs[32][132];

    int type = blockIdx.z;
    const float* A = (type == 1 || type == 2) ? kvin : qin;
    const float* W = (type == 0) ? w_q : (type == 1) ? w_k
                   : (type == 2) ? w_v : w_g;
    float* Out = (type == 0) ? g_Q : (type == 1) ? g_K
               : (type == 2) ? g_V : g_G;

    int t = threadIdx.x;
    int bM = blockIdx.x * 128;
    int bN = blockIdx.y * 128;
    int lane = t & 31, w = t >> 5;
    int warpM = w >> 2, warpN = w & 3;      // 2 x 4 warp grid
    int gid = lane >> 2, tid = lane & 3;

    float acc[4][4][4];
#pragma unroll
    for (int i = 0; i < 4; i++)
#pragma unroll
        for (int j = 0; j < 4; j++)
#pragma unroll
            for (int r = 0; r < 4; r++) acc[i][j][r] = 0.f;

    float4 av[4], bv[4];
    // prefetch first k-chunk
#pragma unroll
    for (int p = 0; p < 4; p++) {
        int idx = t + p * 256;
        av[p] = *(const float4*)&A[(bM + (idx >> 3)) * 256 + (idx & 7) * 4];
        bv[p] = *(const float4*)&W[(idx >> 5) * 256 + bN + (idx & 31) * 4];
    }

    for (int kt = 0; kt < 8; kt++) {
        // store current chunk to SMEM (with tf32 rounding)
#pragma unroll
        for (int p = 0; p < 4; p++) {
            int idx = t + p * 256;
            int ar = idx >> 3, ac = (idx & 7) * 4;
            As[ar][ac + 0] = f2tf(av[p].x);
            As[ar][ac + 1] = f2tf(av[p].y);
            As[ar][ac + 2] = f2tf(av[p].z);
            As[ar][ac + 3] = f2tf(av[p].w);
            int br = idx >> 5, bc = (idx & 31) * 4;
            Bs[br][bc + 0] = f2tf(bv[p].x);
            Bs[br][bc + 1] = f2tf(bv[p].y);
            Bs[br][bc + 2] = f2tf(bv[p].z);
            Bs[br][bc + 3] = f2tf(bv[p].w);
        }
        __syncthreads();

        // prefetch next chunk
        if (kt < 7) {
            int kc = (kt + 1) * 32;
#pragma unroll
            for (int p = 0; p < 4; p++) {
                int idx = t + p * 256;
                av[p] = *(const float4*)&A[(bM + (idx >> 3)) * 256 + kc + (idx & 7) * 4];
                bv[p] = *(const float4*)&W[(kc + (idx >> 5)) * 256 + bN + (idx & 31) * 4];
            }
        }

        // 4 k-steps of 8
#pragma unroll
        for (int ks = 0; ks < 4; ks++) {
            int kk = ks * 8;
            uint32_t af[4][4], bf[4][2];
#pragma unroll
            for (int i = 0; i < 4; i++) {
                int r0 = warpM * 64 + i * 16;
                af[i][0] = As[r0 + gid][kk + tid];
                af[i][1] = As[r0 + gid + 8][kk + tid];
                af[i][2] = As[r0 + gid][kk + tid + 4];
                af[i][3] = As[r0 + gid + 8][kk + tid + 4];
            }
#pragma unroll
            for (int j = 0; j < 4; j++) {
                int c0 = warpN * 32 + j * 8 + gid;
                bf[j][0] = Bs[kk + tid][c0];
                bf[j][1] = Bs[kk + tid + 4][c0];
            }
#pragma unroll
            for (int i = 0; i < 4; i++)
#pragma unroll
                for (int j = 0; j < 4; j++)
                    mma_tf32(acc[i][j], af[i][0], af[i][1], af[i][2], af[i][3],
                             bf[j][0], bf[j][1]);
        }
        __syncthreads();
    }

    // epilogue: [s][h][r][d] layout, per-type transforms
    float norm = 0.17677669529663687f;  // 1/sqrt(32)
#pragma unroll
    for (int i = 0; i < 4; i++) {
#pragma unroll
        for (int j = 0; j < 4; j++) {
            int r0 = bM + warpM * 64 + i * 16 + gid;
            int c0 = bN + warpN * 32 + j * 8 + tid * 2;
#pragma unroll
            for (int e = 0; e < 4; e++) {
                int row = r0 + (e >> 1) * 8;
                int col = c0 + (e & 1);
                float v = acc[i][j][e];
                if (type == 0) v *= norm;
                if (type == 3) v = 1.f / (1.f + __expf(-(v + b_g[col])));
                int s = row >> 8, rr = row & 255;
                int h = col >> 5, d = col & 31;
                Out[((s * 8 + h) * 256 + rr) * 32 + d] = v;
            }
        }
    }
}

// ---------------------------------------------------------------------------
// Kernel 3: attention per (s, h) — unchanged fp32 version.
// ---------------------------------------------------------------------------
__global__ void attn_kernel(const float* __restrict__ bias_mask) {
    extern __shared__ float sm[];
    float* Ks = sm;                          // 256*32
    float* Vs = sm + 8192;                   // 256*32
    float* Bb = sm + 16384;                  // 256*33 (padded)
    float* Mb = sm + 16384 + 256 * 33;       // 256

    int s = blockIdx.x, h = blockIdx.y;
    int t = threadIdx.x;

    const float4* Kg = (const float4*)(g_K + (s * 8 + h) * R_DIM * D_DIM);
    const float4* Vg = (const float4*)(g_V + (s * 8 + h) * R_DIM * D_DIM);
#pragma unroll
    for (int i = t; i < 2048; i += 256) {
        ((float4*)Ks)[i] = Kg[i];
        ((float4*)Vs)[i] = Vg[i];
    }
    Mb[t] = (bias_mask[s * 256 + t] - 1.f) * 1e9f;

    float qreg[32];
    const float4* Qg = (const float4*)(g_Q + ((s * 8 + h) * R_DIM + t) * D_DIM);
#pragma unroll
    for (int i = 0; i < 8; i++) {
        float4 v = Qg[i];
        qreg[i * 4 + 0] = v.x; qreg[i * 4 + 1] = v.y;
        qreg[i * 4 + 2] = v.z; qreg[i * 4 + 3] = v.w;
    }

    float l = 0.f;
    float acc[32];
#pragma unroll
    for (int d = 0; d < 32; d++) acc[d] = 0.f;

    const float* biasBase = g_biasT + (h * 256) * 256;

    for (int kc = 0; kc < 256; kc += 32) {
        __syncthreads();
        for (int f = t; f < 2048; f += 256) {
            int qq = f >> 3, k4 = (f & 7) * 4;
            float4 v = *(const float4*)&biasBase[qq * 256 + kc + k4];
            Bb[qq * 33 + k4 + 0] = v.x;
            Bb[qq * 33 + k4 + 1] = v.y;
            Bb[qq * 33 + k4 + 2] = v.z;
            Bb[qq * 33 + k4 + 3] = v.w;
        }
        __syncthreads();
#pragma unroll 4
        for (int kk = 0; kk < 32; kk++) {
            int k = kc + kk;
            const float* Kr = Ks + k * 32;
            float s0 = 0.f, s1 = 0.f, s2 = 0.f, s3 = 0.f;
#pragma unroll
            for (int d = 0; d < 32; d += 4) {
                s0 += qreg[d + 0] * Kr[d + 0];
                s1 += qreg[d + 1] * Kr[d + 1];
                s2 += qreg[d + 2] * Kr[d + 2];
                s3 += qreg[d + 3] * Kr[d + 3];
            }
            float sc = Bb[t * 33 + kk] + Mb[k] + ((s0 + s1) + (s2 + s3));
            float p = __expf(sc);
            l += p;
            const float* Vr = Vs + k * 32;
#pragma unroll
            for (int d = 0; d < 32; d++) acc[d] += p * Vr[d];
        }
    }

    float inv = 1.f / l;
    float* Og = g_O + ((s * 8 + h) * R_DIM + t) * D_DIM;
#pragma unroll
    for (int d = 0; d < 32; d++) Og[d] = acc[d] * inv;
}

// ---------------------------------------------------------------------------
// Kernel 4: out = (O*G) @ Wo + b_o via tf32 mma.sync (same tiling as proj).
// A tile formed as O*G on the fly during global load.
// ---------------------------------------------------------------------------
__global__ void __launch_bounds__(256)
outproj_mma_kernel(const float* __restrict__ w_o,
                   const float* __restrict__ b_o,
                   float* __restrict__ out) {
    __shared__ uint32_t As[128][36];
    __shared__ uint32_t Bs[32][132];

    int t = threadIdx.x;
    int bM = blockIdx.x * 128;
    int bN = blockIdx.y * 128;
    int lane = t & 31, w = t >> 5;
    int warpM = w >> 2, warpN = w & 3;
    int gid = lane >> 2, tid = lane & 3;

    float acc[4][4][4];
#pragma unroll
    for (int i = 0; i < 4; i++)
#pragma unroll
        for (int j = 0; j < 4; j++)
#pragma unroll
            for (int r = 0; r < 4; r++) acc[i][j][r] = 0.f;

    float4 av[4], bv[4];

    auto loadA = [&](int kc, int p) -> float4 {
        int idx = t + p * 256;
        int m = bM + (idx >> 3);
        int s = m >> 8, rr = m & 255;
        int h = kc >> 5;                 // kc multiple of 32
        int d0 = (idx & 7) * 4;
        int base = (((s * 8 + h) * 256 + rr) * 32 + d0) >> 2;
        float4 ov = ((const float4*)g_O)[base];
        float4 gv = ((const float4*)g_G)[base];
        float4 r;
        r.x = ov.x * gv.x; r.y = ov.y * gv.y;
        r.z = ov.z * gv.z; r.w = ov.w * gv.w;
        return r;
    };

#pragma unroll
    for (int p = 0; p < 4; p++) {
        int idx = t + p * 256;
        av[p] = loadA(0, p);
        bv[p] = *(const float4*)&w_o[(idx >> 5) * 256 + bN + (idx & 31) * 4];
    }

    for (int kt = 0; kt < 8; kt++) {
#pragma unroll
        for (int p = 0; p < 4; p++) {
            int idx = t + p * 256;
            int ar = idx >> 3, ac = (idx & 7) * 4;
            As[ar][ac + 0] = f2tf(av[p].x);
            As[ar][ac + 1] = f2tf(av[p].y);
            As[ar][ac + 2] = f2tf(av[p].z);
            As[ar][ac + 3] = f2tf(av[p].w);
            int br = idx >> 5, bc = (idx & 31) * 4;
            Bs[br][bc + 0] = f2tf(bv[p].x);
            Bs[br][bc + 1] = f2tf(bv[p].y);
            Bs[br][bc + 2] = f2tf(bv[p].z);
            Bs[br][bc + 3] = f2tf(bv[p].w);
        }
        __syncthreads();

        if (kt < 7) {
            int kc = (kt + 1) * 32;
#pragma unroll
            for (int p = 0; p < 4; p++) {
                int idx = t + p * 256;
                av[p] = loadA(kc, p);
                bv[p] = *(const float4*)&w_o[(kc + (idx >> 5)) * 256 + bN + (idx & 31) * 4];
            }
        }

#pragma unroll
        for (int ks = 0; ks < 4; ks++) {
            int kk = ks * 8;
            uint32_t af[4][4], bf[4][2];
#pragma unroll
            for (int i = 0; i < 4; i++) {
                int r0 = warpM * 64 + i * 16;
                af[i][0] = As[r0 + gid][kk + tid];
                af[i][1] = As[r0 + gid + 8][kk + tid];
                af[i][2] = As[r0 + gid][kk + tid + 4];
                af[i][3] = As[r0 + gid + 8][kk + tid + 4];
            }
#pragma unroll
            for (int j = 0; j < 4; j++) {
                int c0 = warpN * 32 + j * 8 + gid;
                bf[j][0] = Bs[kk + tid][c0];
                bf[j][1] = Bs[kk + tid + 4][c0];
            }
#pragma unroll
            for (int i = 0; i < 4; i++)
#pragma unroll
                for (int j = 0; j < 4; j++)
                    mma_tf32(acc[i][j], af[i][0], af[i][1], af[i][2], af[i][3],
                             bf[j][0], bf[j][1]);
        }
        __syncthreads();
    }

#pragma unroll
    for (int i = 0; i < 4; i++) {
#pragma unroll
        for (int j = 0; j < 4; j++) {
            int r0 = bM + warpM * 64 + i * 16 + gid;
            int c0 = bN + warpN * 32 + j * 8 + tid * 2;
#pragma unroll
            for (int e = 0; e < 4; e++) {
                int row = r0 + (e >> 1) * 8;
                int col = c0 + (e & 1);
                out[row * 256 + col] = acc[i][j][e] + b_o[col];
            }
        }
    }
}

// ---------------------------------------------------------------------------
extern "C" void kernel_launch(void* const* d_in, const int* in_sizes, int n_in,
                              void* d_out, int out_size) {
    const float* q    = (const float*)d_in[0];
    const float* kv   = (const float*)d_in[1];
    const float* bias = (const float*)d_in[2];
    const float* mask = (const float*)d_in[3];
    const float* w_q  = (const float*)d_in[4];
    const float* w_k  = (const float*)d_in[5];
    const float* w_v  = (const float*)d_in[6];
    const float* w_g  = (const float*)d_in[7];
    const float* b_g  = (const float*)d_in[8];
    const float* w_o  = (const float*)d_in[9];
    const float* b_o  = (const float*)d_in[10];
    float* out = (float*)d_out;

    bias_transpose_kernel<<<(H_DIM * R_DIM * R_DIM + 255) / 256, 256>>>(bias);

    proj_mma_kernel<<<dim3(SR_DIM / 128, HD_DIM / 128, 4), 256>>>(
        q, kv, w_q, w_k, w_v, w_g, b_g);

    const int ATTN_SMEM = (8192 + 8192 + 256 * 33 + 256) * 4;  // 100352 B
    cudaFuncSetAttribute(attn_kernel,
                         cudaFuncAttributeMaxDynamicSharedMemorySize, ATTN_SMEM);
    attn_kernel<<<dim3(S_DIM, H_DIM), 256, ATTN_SMEM>>>(mask);

    outproj_mma_kernel<<<dim3(SR_DIM / 128, C_DIM / 128), 256>>>(w_o, b_o, out);
}

// round 5
// speedup vs baseline: 1.5905x; 1.0041x over previous
#include <cuda_runtime.h>
#include <math.h>
#include <stdint.h>

#define S_DIM 128
#define R_DIM 256
#define C_DIM 256
#define H_DIM 8
#define D_DIM 32
#define HD_DIM 256
#define SR_DIM (S_DIM * R_DIM)

// Scratch (device globals; allocation-free contract)
__device__ float g_Q[S_DIM * H_DIM * R_DIM * D_DIM];   // [s][h][r][d]
__device__ float g_K[S_DIM * H_DIM * R_DIM * D_DIM];
__device__ float g_V[S_DIM * H_DIM * R_DIM * D_DIM];
__device__ float g_G[S_DIM * H_DIM * R_DIM * D_DIM];
__device__ float g_O[S_DIM * H_DIM * R_DIM * D_DIM];
__device__ float g_biasT[H_DIM * R_DIM * R_DIM];       // [h][q][k]

// ---------------------------------------------------------------------------
// TF32 helpers
// ---------------------------------------------------------------------------
__device__ __forceinline__ uint32_t f2tf(float f) {
    uint32_t u;
    asm("cvt.rna.tf32.f32 %0, %1;" : "=r"(u) : "f"(f));
    return u;
}

__device__ __forceinline__ void mma_tf32(float c[4],
                                         uint32_t a0, uint32_t a1,
                                         uint32_t a2, uint32_t a3,
                                         uint32_t b0, uint32_t b1) {
    asm volatile(
        "mma.sync.aligned.m16n8k8.row.col.f32.tf32.tf32.f32 "
        "{%0,%1,%2,%3}, {%4,%5,%6,%7}, {%8,%9}, {%0,%1,%2,%3};"
        : "+f"(c[0]), "+f"(c[1]), "+f"(c[2]), "+f"(c[3])
        : "r"(a0), "r"(a1), "r"(a2), "r"(a3), "r"(b0), "r"(b1));
}

// ---------------------------------------------------------------------------
// Kernel 1: bias [q][k][h] -> biasT [h][q][k]
// ---------------------------------------------------------------------------
__global__ void bias_transpose_kernel(const float* __restrict__ bias) {
    int idx = blockIdx.x * blockDim.x + threadIdx.x;
    if (idx < H_DIM * R_DIM * R_DIM) {
        int k  = idx & 255;
        int qq = (idx >> 8) & 255;
        int h  = idx >> 16;
        g_biasT[idx] = bias[((qq << 8) + k) * 8 + h];
    }
}

// ---------------------------------------------------------------------------
// Kernel 2: fused projections via tf32 mma.sync.
// C[M=32768, N=256] = A[M,256] * W[256,256]; type z: 0=Q(*norm) 1=K 2=V
// 3=G(sigmoid+b_g). Block 128x128, BK=32, 8 warps of 64x32 warp tiles.
// ---------------------------------------------------------------------------
__global__ void __launch_bounds__(256)
proj_mma_kernel(const float* __restrict__ qin,
                const float* __restrict__ kvin,
                const float* __restrict__ w_q,
                const float* __restrict__ w_k,
                const float* __restrict__ w_v,
                const float* __restrict__ w_g,
                const float* __restrict__ b_g) {
    __shared__ uint32_t As[128][36];   // padded: frag reads conflict-free
    __shared__ uint32_t Bs[32][132];

    int type = blockIdx.z;
    const float* A = (type == 1 || type == 2) ? kvin : qin;
    const float* W = (type == 0) ? w_q : (type == 1) ? w_k
                   : (type == 2) ? w_v : w_g;
    float* Out = (type == 0) ? g_Q : (type == 1) ? g_K
               : (type == 2) ? g_V : g_G;

    int t = threadIdx.x;
    int bM = blockIdx.x * 128;
    int bN = blockIdx.y * 128;
    int lane = t & 31, w = t >> 5;
    int warpM = w >> 2, warpN = w & 3;      // 2 x 4 warp grid
    int gid = lane >> 2, tid = lane & 3;

    float acc[4][4][4];
#pragma unroll
    for (int i = 0; i < 4; i++)
#pragma unroll
        for (int j = 0; j < 4; j++)
#pragma unroll
            for (int r = 0; r < 4; r++) acc[i][j][r] = 0.f;

    float4 av[4], bv[4];
    // prefetch first k-chunk
#pragma unroll
    for (int p = 0; p < 4; p++) {
        int idx = t + p * 256;
        av[p] = *(const float4*)&A[(bM + (idx >> 3)) * 256 + (idx & 7) * 4];
        bv[p] = *(const float4*)&W[(idx >> 5) * 256 + bN + (idx & 31) * 4];
    }

    for (int kt = 0; kt < 8; kt++) {
        // store current chunk to SMEM (with tf32 rounding)
#pragma unroll
        for (int p = 0; p < 4; p++) {
            int idx = t + p * 256;
            int ar = idx >> 3, ac = (idx & 7) * 4;
            As[ar][ac + 0] = f2tf(av[p].x);
            As[ar][ac + 1] = f2tf(av[p].y);
            As[ar][ac + 2] = f2tf(av[p].z);
            As[ar][ac + 3] = f2tf(av[p].w);
            int br = idx >> 5, bc = (idx & 31) * 4;
            Bs[br][bc + 0] = f2tf(bv[p].x);
            Bs[br][bc + 1] = f2tf(bv[p].y);
            Bs[br][bc + 2] = f2tf(bv[p].z);
            Bs[br][bc + 3] = f2tf(bv[p].w);
        }
        __syncthreads();

        // prefetch next chunk
        if (kt < 7) {
            int kc = (kt + 1) * 32;
#pragma unroll
            for (int p = 0; p < 4; p++) {
                int idx = t + p * 256;
                av[p] = *(const float4*)&A[(bM + (idx >> 3)) * 256 + kc + (idx & 7) * 4];
                bv[p] = *(const float4*)&W[(kc + (idx >> 5)) * 256 + bN + (idx & 31) * 4];
            }
        }

        // 4 k-steps of 8
#pragma unroll
        for (int ks = 0; ks < 4; ks++) {
            int kk = ks * 8;
            uint32_t af[4][4], bf[4][2];
#pragma unroll
            for (int i = 0; i < 4; i++) {
                int r0 = warpM * 64 + i * 16;
                af[i][0] = As[r0 + gid][kk + tid];
                af[i][1] = As[r0 + gid + 8][kk + tid];
                af[i][2] = As[r0 + gid][kk + tid + 4];
                af[i][3] = As[r0 + gid + 8][kk + tid + 4];
            }
#pragma unroll
            for (int j = 0; j < 4; j++) {
                int c0 = warpN * 32 + j * 8 + gid;
                bf[j][0] = Bs[kk + tid][c0];
                bf[j][1] = Bs[kk + tid + 4][c0];
            }
#pragma unroll
            for (int i = 0; i < 4; i++)
#pragma unroll
                for (int j = 0; j < 4; j++)
                    mma_tf32(acc[i][j], af[i][0], af[i][1], af[i][2], af[i][3],
                             bf[j][0], bf[j][1]);
        }
        __syncthreads();
    }

    // epilogue: [s][h][r][d] layout, per-type transforms
    float norm = 0.17677669529663687f;  // 1/sqrt(32)
#pragma unroll
    for (int i = 0; i < 4; i++) {
#pragma unroll
        for (int j = 0; j < 4; j++) {
            int r0 = bM + warpM * 64 + i * 16 + gid;
            int c0 = bN + warpN * 32 + j * 8 + tid * 2;
#pragma unroll
            for (int e = 0; e < 4; e++) {
                int row = r0 + (e >> 1) * 8;
                int col = c0 + (e & 1);
                float v = acc[i][j][e];
                if (type == 0) v *= norm;
                if (type == 3) v = 1.f / (1.f + __expf(-(v + b_g[col])));
                int s = row >> 8, rr = row & 255;
                int h = col >> 5, d = col & 31;
                Out[((s * 8 + h) * 256 + rr) * 32 + d] = v;
            }
        }
    }
}

// ---------------------------------------------------------------------------
// Kernel 3: attention per (s, h) — unchanged fp32 version.
// ---------------------------------------------------------------------------
__global__ void attn_kernel(const float* __restrict__ bias_mask) {
    extern __shared__ float sm[];
    float* Ks = sm;                          // 256*32
    float* Vs = sm + 8192;                   // 256*32
    float* Bb = sm + 16384;                  // 256*33 (padded)
    float* Mb = sm + 16384 + 256 * 33;       // 256

    int s = blockIdx.x, h = blockIdx.y;
    int t = threadIdx.x;

    const float4* Kg = (const float4*)(g_K + (s * 8 + h) * R_DIM * D_DIM);
    const float4* Vg = (const float4*)(g_V + (s * 8 + h) * R_DIM * D_DIM);
#pragma unroll
    for (int i = t; i < 2048; i += 256) {
        ((float4*)Ks)[i] = Kg[i];
        ((float4*)Vs)[i] = Vg[i];
    }
    Mb[t] = (bias_mask[s * 256 + t] - 1.f) * 1e9f;

    float qreg[32];
    const float4* Qg = (const float4*)(g_Q + ((s * 8 + h) * R_DIM + t) * D_DIM);
#pragma unroll
    for (int i = 0; i < 8; i++) {
        float4 v = Qg[i];
        qreg[i * 4 + 0] = v.x; qreg[i * 4 + 1] = v.y;
        qreg[i * 4 + 2] = v.z; qreg[i * 4 + 3] = v.w;
    }

    float l = 0.f;
    float acc[32];
#pragma unroll
    for (int d = 0; d < 32; d++) acc[d] = 0.f;

    const float* biasBase = g_biasT + (h * 256) * 256;

    for (int kc = 0; kc < 256; kc += 32) {
        __syncthreads();
        for (int f = t; f < 2048; f += 256) {
            int qq = f >> 3, k4 = (f & 7) * 4;
            float4 v = *(const float4*)&biasBase[qq * 256 + kc + k4];
            Bb[qq * 33 + k4 + 0] = v.x;
            Bb[qq * 33 + k4 + 1] = v.y;
            Bb[qq * 33 + k4 + 2] = v.z;
            Bb[qq * 33 + k4 + 3] = v.w;
        }
        __syncthreads();
#pragma unroll 4
        for (int kk = 0; kk < 32; kk++) {
            int k = kc + kk;
            const float* Kr = Ks + k * 32;
            float s0 = 0.f, s1 = 0.f, s2 = 0.f, s3 = 0.f;
#pragma unroll
            for (int d = 0; d < 32; d += 4) {
                s0 += qreg[d + 0] * Kr[d + 0];
                s1 += qreg[d + 1] * Kr[d + 1];
                s2 += qreg[d + 2] * Kr[d + 2];
                s3 += qreg[d + 3] * Kr[d + 3];
            }
            float sc = Bb[t * 33 + kk] + Mb[k] + ((s0 + s1) + (s2 + s3));
            float p = __expf(sc);
            l += p;
            const float* Vr = Vs + k * 32;
#pragma unroll
            for (int d = 0; d < 32; d++) acc[d] += p * Vr[d];
        }
    }

    float inv = 1.f / l;
    float* Og = g_O + ((s * 8 + h) * R_DIM + t) * D_DIM;
#pragma unroll
    for (int d = 0; d < 32; d++) Og[d] = acc[d] * inv;
}

// ---------------------------------------------------------------------------
// Kernel 4: out = (O*G) @ Wo + b_o via tf32 mma.sync (same tiling as proj).
// A tile formed as O*G on the fly during global load.
// ---------------------------------------------------------------------------
__global__ void __launch_bounds__(256)
outproj_mma_kernel(const float* __restrict__ w_o,
                   const float* __restrict__ b_o,
                   float* __restrict__ out) {
    __shared__ uint32_t As[128][36];
    __shared__ uint32_t Bs[32][132];

    int t = threadIdx.x;
    int bM = blockIdx.x * 128;
    int bN = blockIdx.y * 128;
    int lane = t & 31, w = t >> 5;
    int warpM = w >> 2, warpN = w & 3;
    int gid = lane >> 2, tid = lane & 3;

    float acc[4][4][4];
#pragma unroll
    for (int i = 0; i < 4; i++)
#pragma unroll
        for (int j = 0; j < 4; j++)
#pragma unroll
            for (int r = 0; r < 4; r++) acc[i][j][r] = 0.f;

    float4 av[4], bv[4];

    auto loadA = [&](int kc, int p) -> float4 {
        int idx = t + p * 256;
        int m = bM + (idx >> 3);
        int s = m >> 8, rr = m & 255;
        int h = kc >> 5;                 // kc multiple of 32
        int d0 = (idx & 7) * 4;
        int base = (((s * 8 + h) * 256 + rr) * 32 + d0) >> 2;
        float4 ov = ((const float4*)g_O)[base];
        float4 gv = ((const float4*)g_G)[base];
        float4 r;
        r.x = ov.x * gv.x; r.y = ov.y * gv.y;
        r.z = ov.z * gv.z; r.w = ov.w * gv.w;
        return r;
    };

#pragma unroll
    for (int p = 0; p < 4; p++) {
        int idx = t + p * 256;
        av[p] = loadA(0, p);
        bv[p] = *(const float4*)&w_o[(idx >> 5) * 256 + bN + (idx & 31) * 4];
    }

    for (int kt = 0; kt < 8; kt++) {
#pragma unroll
        for (int p = 0; p < 4; p++) {
            int idx = t + p * 256;
            int ar = idx >> 3, ac = (idx & 7) * 4;
            As[ar][ac + 0] = f2tf(av[p].x);
            As[ar][ac + 1] = f2tf(av[p].y);
            As[ar][ac + 2] = f2tf(av[p].z);
            As[ar][ac + 3] = f2tf(av[p].w);
            int br = idx >> 5, bc = (idx & 31) * 4;
            Bs[br][bc + 0] = f2tf(bv[p].x);
            Bs[br][bc + 1] = f2tf(bv[p].y);
            Bs[br][bc + 2] = f2tf(bv[p].z);
            Bs[br][bc + 3] = f2tf(bv[p].w);
        }
        __syncthreads();

        if (kt < 7) {
            int kc = (kt + 1) * 32;
#pragma unroll
            for (int p = 0; p < 4; p++) {
                int idx = t + p * 256;
                av[p] = loadA(kc, p);
                bv[p] = *(const float4*)&w_o[(kc + (idx >> 5)) * 256 + bN + (idx & 31) * 4];
            }
        }

#pragma unroll
        for (int ks = 0; ks < 4; ks++) {
            int kk = ks * 8;
            uint32_t af[4][4], bf[4][2];
#pragma unroll
            for (int i = 0; i < 4; i++) {
                int r0 = warpM * 64 + i * 16;
                af[i][0] = As[r0 + gid][kk + tid];
                af[i][1] = As[r0 + gid + 8][kk + tid];
                af[i][2] = As[r0 + gid][kk + tid + 4];
                af[i][3] = As[r0 + gid + 8][kk + tid + 4];
            }
#pragma unroll
            for (int j = 0; j < 4; j++) {
                int c0 = warpN * 32 + j * 8 + gid;
                bf[j][0] = Bs[kk + tid][c0];
                bf[j][1] = Bs[kk + tid + 4][c0];
            }
#pragma unroll
            for (int i = 0; i < 4; i++)
#pragma unroll
                for (int j = 0; j < 4; j++)
                    mma_tf32(acc[i][j], af[i][0], af[i][1], af[i][2], af[i][3],
                             bf[j][0], bf[j][1]);
        }
        __syncthreads();
    }

#pragma unroll
    for (int i = 0; i < 4; i++) {
#pragma unroll
        for (int j = 0; j < 4; j++) {
            int r0 = bM + warpM * 64 + i * 16 + gid;
            int c0 = bN + warpN * 32 + j * 8 + tid * 2;
#pragma unroll
            for (int e = 0; e < 4; e++) {
                int row = r0 + (e >> 1) * 8;
                int col = c0 + (e & 1);
                out[row * 256 + col] = acc[i][j][e] + b_o[col];
            }
        }
    }
}

// ---------------------------------------------------------------------------
extern "C" void kernel_launch(void* const* d_in, const int* in_sizes, int n_in,
                              void* d_out, int out_size) {
    const float* q    = (const float*)d_in[0];
    const float* kv   = (const float*)d_in[1];
    const float* bias = (const float*)d_in[2];
    const float* mask = (const float*)d_in[3];
    const float* w_q  = (const float*)d_in[4];
    const float* w_k  = (const float*)d_in[5];
    const float* w_v  = (const float*)d_in[6];
    const float* w_g  = (const float*)d_in[7];
    const float* b_g  = (const float*)d_in[8];
    const float* w_o  = (const float*)d_in[9];
    const float* b_o  = (const float*)d_in[10];
    float* out = (float*)d_out;

    bias_transpose_kernel<<<(H_DIM * R_DIM * R_DIM + 255) / 256, 256>>>(bias);

    proj_mma_kernel<<<dim3(SR_DIM / 128, HD_DIM / 128, 4), 256>>>(
        q, kv, w_q, w_k, w_v, w_g, b_g);

    const int ATTN_SMEM = (8192 + 8192 + 256 * 33 + 256) * 4;  // 100352 B
    cudaFuncSetAttribute(attn_kernel,
                         cudaFuncAttributeMaxDynamicSharedMemorySize, ATTN_SMEM);
    attn_kernel<<<dim3(S_DIM, H_DIM), 256, ATTN_SMEM>>>(mask);

    outproj_mma_kernel<<<dim3(SR_DIM / 128, C_DIM / 128), 256>>>(w_o, b_o, out);
}

// round 6
// speedup vs baseline: 2.4639x; 1.5491x over previous
#include <cuda_runtime.h>
#include <math.h>
#include <stdint.h>

#define S_DIM 128
#define R_DIM 256
#define C_DIM 256
#define H_DIM 8
#define D_DIM 32
#define HD_DIM 256
#define SR_DIM (S_DIM * R_DIM)

// Scratch (device globals; allocation-free contract)
__device__ float g_Q[S_DIM * H_DIM * R_DIM * D_DIM];   // [s][h][r][d]
__device__ float g_K[S_DIM * H_DIM * R_DIM * D_DIM];
__device__ float g_V[S_DIM * H_DIM * R_DIM * D_DIM];
__device__ float g_G[S_DIM * H_DIM * R_DIM * D_DIM];
__device__ float g_O[S_DIM * H_DIM * R_DIM * D_DIM];
__device__ float g_biasT[H_DIM * R_DIM * R_DIM];       // [h][q][k]

// ---------------------------------------------------------------------------
// TF32 helpers
// ---------------------------------------------------------------------------
__device__ __forceinline__ uint32_t f2tf(float f) {
    uint32_t u;
    asm("cvt.rna.tf32.f32 %0, %1;" : "=r"(u) : "f"(f));
    return u;
}

__device__ __forceinline__ void mma_tf32(float c[4],
                                         uint32_t a0, uint32_t a1,
                                         uint32_t a2, uint32_t a3,
                                         uint32_t b0, uint32_t b1) {
    asm volatile(
        "mma.sync.aligned.m16n8k8.row.col.f32.tf32.tf32.f32 "
        "{%0,%1,%2,%3}, {%4,%5,%6,%7}, {%8,%9}, {%0,%1,%2,%3};"
        : "+f"(c[0]), "+f"(c[1]), "+f"(c[2]), "+f"(c[3])
        : "r"(a0), "r"(a1), "r"(a2), "r"(a3), "r"(b0), "r"(b1));
}

// ---------------------------------------------------------------------------
// Kernel 1: bias [q][k][h] -> biasT [h][q][k]
// ---------------------------------------------------------------------------
__global__ void bias_transpose_kernel(const float* __restrict__ bias) {
    int idx = blockIdx.x * blockDim.x + threadIdx.x;
    if (idx < H_DIM * R_DIM * R_DIM) {
        int k  = idx & 255;
        int qq = (idx >> 8) & 255;
        int h  = idx >> 16;
        g_biasT[idx] = bias[((qq << 8) + k) * 8 + h];
    }
}

// ---------------------------------------------------------------------------
// Kernel 2: fused projections via tf32 mma.sync (unchanged from R5).
// ---------------------------------------------------------------------------
__global__ void __launch_bounds__(256)
proj_mma_kernel(const float* __restrict__ qin,
                const float* __restrict__ kvin,
                const float* __restrict__ w_q,
                const float* __restrict__ w_k,
                const float* __restrict__ w_v,
                const float* __restrict__ w_g,
                const float* __restrict__ b_g) {
    __shared__ uint32_t As[128][36];
    __shared__ uint32_t Bs[32][132];

    int type = blockIdx.z;
    const float* A = (type == 1 || type == 2) ? kvin : qin;
    const float* W = (type == 0) ? w_q : (type == 1) ? w_k
                   : (type == 2) ? w_v : w_g;
    float* Out = (type == 0) ? g_Q : (type == 1) ? g_K
               : (type == 2) ? g_V : g_G;

    int t = threadIdx.x;
    int bM = blockIdx.x * 128;
    int bN = blockIdx.y * 128;
    int lane = t & 31, w = t >> 5;
    int warpM = w >> 2, warpN = w & 3;
    int gid = lane >> 2, tid = lane & 3;

    float acc[4][4][4];
#pragma unroll
    for (int i = 0; i < 4; i++)
#pragma unroll
        for (int j = 0; j < 4; j++)
#pragma unroll
            for (int r = 0; r < 4; r++) acc[i][j][r] = 0.f;

    float4 av[4], bv[4];
#pragma unroll
    for (int p = 0; p < 4; p++) {
        int idx = t + p * 256;
        av[p] = *(const float4*)&A[(bM + (idx >> 3)) * 256 + (idx & 7) * 4];
        bv[p] = *(const float4*)&W[(idx >> 5) * 256 + bN + (idx & 31) * 4];
    }

    for (int kt = 0; kt < 8; kt++) {
#pragma unroll
        for (int p = 0; p < 4; p++) {
            int idx = t + p * 256;
            int ar = idx >> 3, ac = (idx & 7) * 4;
            As[ar][ac + 0] = f2tf(av[p].x);
            As[ar][ac + 1] = f2tf(av[p].y);
            As[ar][ac + 2] = f2tf(av[p].z);
            As[ar][ac + 3] = f2tf(av[p].w);
            int br = idx >> 5, bc = (idx & 31) * 4;
            Bs[br][bc + 0] = f2tf(bv[p].x);
            Bs[br][bc + 1] = f2tf(bv[p].y);
            Bs[br][bc + 2] = f2tf(bv[p].z);
            Bs[br][bc + 3] = f2tf(bv[p].w);
        }
        __syncthreads();

        if (kt < 7) {
            int kc = (kt + 1) * 32;
#pragma unroll
            for (int p = 0; p < 4; p++) {
                int idx = t + p * 256;
                av[p] = *(const float4*)&A[(bM + (idx >> 3)) * 256 + kc + (idx & 7) * 4];
                bv[p] = *(const float4*)&W[(kc + (idx >> 5)) * 256 + bN + (idx & 31) * 4];
            }
        }

#pragma unroll
        for (int ks = 0; ks < 4; ks++) {
            int kk = ks * 8;
            uint32_t af[4][4], bf[4][2];
#pragma unroll
            for (int i = 0; i < 4; i++) {
                int r0 = warpM * 64 + i * 16;
                af[i][0] = As[r0 + gid][kk + tid];
                af[i][1] = As[r0 + gid + 8][kk + tid];
                af[i][2] = As[r0 + gid][kk + tid + 4];
                af[i][3] = As[r0 + gid + 8][kk + tid + 4];
            }
#pragma unroll
            for (int j = 0; j < 4; j++) {
                int c0 = warpN * 32 + j * 8 + gid;
                bf[j][0] = Bs[kk + tid][c0];
                bf[j][1] = Bs[kk + tid + 4][c0];
            }
#pragma unroll
            for (int i = 0; i < 4; i++)
#pragma unroll
                for (int j = 0; j < 4; j++)
                    mma_tf32(acc[i][j], af[i][0], af[i][1], af[i][2], af[i][3],
                             bf[j][0], bf[j][1]);
        }
        __syncthreads();
    }

    float norm = 0.17677669529663687f;
#pragma unroll
    for (int i = 0; i < 4; i++) {
#pragma unroll
        for (int j = 0; j < 4; j++) {
            int r0 = bM + warpM * 64 + i * 16 + gid;
            int c0 = bN + warpN * 32 + j * 8 + tid * 2;
#pragma unroll
            for (int e = 0; e < 4; e++) {
                int row = r0 + (e >> 1) * 8;
                int col = c0 + (e & 1);
                float v = acc[i][j][e];
                if (type == 0) v *= norm;
                if (type == 3) v = 1.f / (1.f + __expf(-(v + b_g[col])));
                int s = row >> 8, rr = row & 255;
                int h = col >> 5, d = col & 31;
                Out[((s * 8 + h) * 256 + rr) * 32 + d] = v;
            }
        }
    }
}

// ---------------------------------------------------------------------------
// Kernel 3: tensor-core attention. One CTA per (s,h); 8 warps x 32 q-rows.
// S = Q K^T via tf32 mma (Q frags register-resident), bias+mask+exp in fp32,
// P staged tf32 in per-warp-private SMEM, O += P V via tf32 mma.
// No __syncthreads in the main loop (only __syncwarp).
// ---------------------------------------------------------------------------
#define ATTN_SMEM_WORDS (9216 + 8320 + 17408 + 256)   // Ks + Vt + Ps + Mb

__global__ void __launch_bounds__(256)
attn_mma_kernel(const float* __restrict__ bias_mask) {
    extern __shared__ uint32_t sm[];
    uint32_t* Ks = sm;                 // [256][36] tf32 K (key, d)
    uint32_t* Vt = sm + 9216;          // [32][260] tf32 V^T (d, key)
    uint32_t* Ps = sm + 17536;         // 8 warps x [32][68] tf32 P
    float*    Mb = (float*)(sm + 34944);  // [256] mask bias

    int s = blockIdx.x, h = blockIdx.y;
    int t = threadIdx.x, lane = t & 31, w = t >> 5;
    int gid = lane >> 2, tid = lane & 3;

    const float* Qg = g_Q + (s * 8 + h) * 8192;
    const float* Kg = g_K + (s * 8 + h) * 8192;
    const float* Vg = g_V + (s * 8 + h) * 8192;

    // ---- stage Q (tf32) into Ps region temporarily: Qs[256][36]
    uint32_t* Qs = Ps;
#pragma unroll
    for (int i = t; i < 2048; i += 256) {
        float4 v = ((const float4*)Qg)[i];
        int r = i >> 3, d = (i & 7) * 4;
        Qs[r * 36 + d + 0] = f2tf(v.x);
        Qs[r * 36 + d + 1] = f2tf(v.y);
        Qs[r * 36 + d + 2] = f2tf(v.z);
        Qs[r * 36 + d + 3] = f2tf(v.w);
    }
    __syncthreads();

    // ---- Q fragments (register resident): warp w owns rows [w*32, w*32+32)
    uint32_t qf[2][4][4];
#pragma unroll
    for (int i2 = 0; i2 < 2; i2++) {
        int r0 = w * 32 + i2 * 16;
#pragma unroll
        for (int ks = 0; ks < 4; ks++) {
            int kk = ks * 8;
            qf[i2][ks][0] = Qs[(r0 + gid) * 36 + kk + tid];
            qf[i2][ks][1] = Qs[(r0 + gid + 8) * 36 + kk + tid];
            qf[i2][ks][2] = Qs[(r0 + gid) * 36 + kk + tid + 4];
            qf[i2][ks][3] = Qs[(r0 + gid + 8) * 36 + kk + tid + 4];
        }
    }
    __syncthreads();

    // ---- stage K (tf32, [key][d]) and V^T (tf32, [d][key]); mask bias
#pragma unroll
    for (int i = t; i < 2048; i += 256) {
        int r = i >> 3, d = (i & 7) * 4;
        float4 kv = ((const float4*)Kg)[i];
        Ks[r * 36 + d + 0] = f2tf(kv.x);
        Ks[r * 36 + d + 1] = f2tf(kv.y);
        Ks[r * 36 + d + 2] = f2tf(kv.z);
        Ks[r * 36 + d + 3] = f2tf(kv.w);
        float4 vv = ((const float4*)Vg)[i];
        Vt[(d + 0) * 260 + r] = f2tf(vv.x);
        Vt[(d + 1) * 260 + r] = f2tf(vv.y);
        Vt[(d + 2) * 260 + r] = f2tf(vv.z);
        Vt[(d + 3) * 260 + r] = f2tf(vv.w);
    }
    Mb[t] = (bias_mask[s * 256 + t] - 1.f) * 1e9f;
    __syncthreads();

    const float* biasBase = g_biasT + h * 65536;
    uint32_t* Pw = Ps + w * 2176;   // this warp's private P tile [32][68]

    float oacc[2][4][4];
#pragma unroll
    for (int i2 = 0; i2 < 2; i2++)
#pragma unroll
        for (int j2 = 0; j2 < 4; j2++)
#pragma unroll
            for (int e = 0; e < 4; e++) oacc[i2][j2][e] = 0.f;
    float rs[2][2] = {{0.f, 0.f}, {0.f, 0.f}};

    for (int kc = 0; kc < 256; kc += 64) {
        // ---- S chunk: [32 q x 64 k]
        float sacc[2][8][4];
#pragma unroll
        for (int i2 = 0; i2 < 2; i2++)
#pragma unroll
            for (int j = 0; j < 8; j++)
#pragma unroll
                for (int e = 0; e < 4; e++) sacc[i2][j][e] = 0.f;

#pragma unroll
        for (int ks = 0; ks < 4; ks++) {
            int kk = ks * 8;
            uint32_t bf[8][2];
#pragma unroll
            for (int j = 0; j < 8; j++) {
                int n = kc + j * 8 + gid;
                bf[j][0] = Ks[n * 36 + kk + tid];
                bf[j][1] = Ks[n * 36 + kk + tid + 4];
            }
#pragma unroll
            for (int i2 = 0; i2 < 2; i2++)
#pragma unroll
                for (int j = 0; j < 8; j++)
                    mma_tf32(sacc[i2][j], qf[i2][ks][0], qf[i2][ks][1],
                             qf[i2][ks][2], qf[i2][ks][3], bf[j][0], bf[j][1]);
        }

        // ---- epilogue: bias + mask + exp; accumulate row sums; P -> SMEM
#pragma unroll
        for (int i2 = 0; i2 < 2; i2++) {
            int qrow = w * 32 + i2 * 16 + gid;
#pragma unroll
            for (int j = 0; j < 8; j++) {
                int col = kc + j * 8 + tid * 2;
                float2 b0 = *(const float2*)(biasBase + qrow * 256 + col);
                float2 b1 = *(const float2*)(biasBase + (qrow + 8) * 256 + col);
                float m0 = Mb[col], m1 = Mb[col + 1];
                float p0 = __expf(sacc[i2][j][0] + b0.x + m0);
                float p1 = __expf(sacc[i2][j][1] + b0.y + m1);
                float p2 = __expf(sacc[i2][j][2] + b1.x + m0);
                float p3 = __expf(sacc[i2][j][3] + b1.y + m1);
                rs[i2][0] += p0 + p1;
                rs[i2][1] += p2 + p3;
                int lr = i2 * 16 + gid, lc = j * 8 + tid * 2;
                Pw[lr * 68 + lc]       = f2tf(p0);
                Pw[lr * 68 + lc + 1]   = f2tf(p1);
                Pw[(lr + 8) * 68 + lc]     = f2tf(p2);
                Pw[(lr + 8) * 68 + lc + 1] = f2tf(p3);
            }
        }
        __syncwarp();

        // ---- O += P V  (k = 64 keys)
#pragma unroll
        for (int ks2 = 0; ks2 < 8; ks2++) {
            int kk = ks2 * 8;
            uint32_t pf[2][4];
#pragma unroll
            for (int i2 = 0; i2 < 2; i2++) {
                int lr = i2 * 16 + gid;
                pf[i2][0] = Pw[lr * 68 + kk + tid];
                pf[i2][1] = Pw[(lr + 8) * 68 + kk + tid];
                pf[i2][2] = Pw[lr * 68 + kk + tid + 4];
                pf[i2][3] = Pw[(lr + 8) * 68 + kk + tid + 4];
            }
            uint32_t vf[4][2];
#pragma unroll
            for (int j2 = 0; j2 < 4; j2++) {
                int d = j2 * 8 + gid;
                vf[j2][0] = Vt[d * 260 + kc + kk + tid];
                vf[j2][1] = Vt[d * 260 + kc + kk + tid + 4];
            }
#pragma unroll
            for (int i2 = 0; i2 < 2; i2++)
#pragma unroll
                for (int j2 = 0; j2 < 4; j2++)
                    mma_tf32(oacc[i2][j2], pf[i2][0], pf[i2][1],
                             pf[i2][2], pf[i2][3], vf[j2][0], vf[j2][1]);
        }
        __syncwarp();   // protect Pw before next chunk's writes
    }

    // ---- reduce row sums across the tid quad (lanes gid*4 .. gid*4+3)
#pragma unroll
    for (int i2 = 0; i2 < 2; i2++)
#pragma unroll
        for (int rp = 0; rp < 2; rp++) {
            float v = rs[i2][rp];
            v += __shfl_xor_sync(0xffffffffu, v, 1);
            v += __shfl_xor_sync(0xffffffffu, v, 2);
            rs[i2][rp] = 1.f / v;
        }

    // ---- normalize and write O [s][h][r][d]
    float* Og = g_O + (s * 8 + h) * 8192;
#pragma unroll
    for (int i2 = 0; i2 < 2; i2++) {
        int r0 = w * 32 + i2 * 16 + gid;
#pragma unroll
        for (int j2 = 0; j2 < 4; j2++) {
            int c = j2 * 8 + tid * 2;
            Og[r0 * 32 + c]           = oacc[i2][j2][0] * rs[i2][0];
            Og[r0 * 32 + c + 1]       = oacc[i2][j2][1] * rs[i2][0];
            Og[(r0 + 8) * 32 + c]     = oacc[i2][j2][2] * rs[i2][1];
            Og[(r0 + 8) * 32 + c + 1] = oacc[i2][j2][3] * rs[i2][1];
        }
    }
}

// ---------------------------------------------------------------------------
// Kernel 4: out = (O*G) @ Wo + b_o via tf32 mma (unchanged from R5).
// ---------------------------------------------------------------------------
__global__ void __launch_bounds__(256)
outproj_mma_kernel(const float* __restrict__ w_o,
                   const float* __restrict__ b_o,
                   float* __restrict__ out) {
    __shared__ uint32_t As[128][36];
    __shared__ uint32_t Bs[32][132];

    int t = threadIdx.x;
    int bM = blockIdx.x * 128;
    int bN = blockIdx.y * 128;
    int lane = t & 31, w = t >> 5;
    int warpM = w >> 2, warpN = w & 3;
    int gid = lane >> 2, tid = lane & 3;

    float acc[4][4][4];
#pragma unroll
    for (int i = 0; i < 4; i++)
#pragma unroll
        for (int j = 0; j < 4; j++)
#pragma unroll
            for (int r = 0; r < 4; r++) acc[i][j][r] = 0.f;

    float4 av[4], bv[4];

    auto loadA = [&](int kc, int p) -> float4 {
        int idx = t + p * 256;
        int m = bM + (idx >> 3);
        int s = m >> 8, rr = m & 255;
        int h = kc >> 5;
        int d0 = (idx & 7) * 4;
        int base = (((s * 8 + h) * 256 + rr) * 32 + d0) >> 2;
        float4 ov = ((const float4*)g_O)[base];
        float4 gv = ((const float4*)g_G)[base];
        float4 r;
        r.x = ov.x * gv.x; r.y = ov.y * gv.y;
        r.z = ov.z * gv.z; r.w = ov.w * gv.w;
        return r;
    };

#pragma unroll
    for (int p = 0; p < 4; p++) {
        int idx = t + p * 256;
        av[p] = loadA(0, p);
        bv[p] = *(const float4*)&w_o[(idx >> 5) * 256 + bN + (idx & 31) * 4];
    }

    for (int kt = 0; kt < 8; kt++) {
#pragma unroll
        for (int p = 0; p < 4; p++) {
            int idx = t + p * 256;
            int ar = idx >> 3, ac = (idx & 7) * 4;
            As[ar][ac + 0] = f2tf(av[p].x);
            As[ar][ac + 1] = f2tf(av[p].y);
            As[ar][ac + 2] = f2tf(av[p].z);
            As[ar][ac + 3] = f2tf(av[p].w);
            int br = idx >> 5, bc = (idx & 31) * 4;
            Bs[br][bc + 0] = f2tf(bv[p].x);
            Bs[br][bc + 1] = f2tf(bv[p].y);
            Bs[br][bc + 2] = f2tf(bv[p].z);
            Bs[br][bc + 3] = f2tf(bv[p].w);
        }
        __syncthreads();

        if (kt < 7) {
            int kc = (kt + 1) * 32;
#pragma unroll
            for (int p = 0; p < 4; p++) {
                int idx = t + p * 256;
                av[p] = loadA(kc, p);
                bv[p] = *(const float4*)&w_o[(kc + (idx >> 5)) * 256 + bN + (idx & 31) * 4];
            }
        }

#pragma unroll
        for (int ks = 0; ks < 4; ks++) {
            int kk = ks * 8;
            uint32_t af[4][4], bf[4][2];
#pragma unroll
            for (int i = 0; i < 4; i++) {
                int r0 = warpM * 64 + i * 16;
                af[i][0] = As[r0 + gid][kk + tid];
                af[i][1] = As[r0 + gid + 8][kk + tid];
                af[i][2] = As[r0 + gid][kk + tid + 4];
                af[i][3] = As[r0 + gid + 8][kk + tid + 4];
            }
#pragma unroll
            for (int j = 0; j < 4; j++) {
                int c0 = warpN * 32 + j * 8 + gid;
                bf[j][0] = Bs[kk + tid][c0];
                bf[j][1] = Bs[kk + tid + 4][c0];
            }
#pragma unroll
            for (int i = 0; i < 4; i++)
#pragma unroll
                for (int j = 0; j < 4; j++)
                    mma_tf32(acc[i][j], af[i][0], af[i][1], af[i][2], af[i][3],
                             bf[j][0], bf[j][1]);
        }
        __syncthreads();
    }

#pragma unroll
    for (int i = 0; i < 4; i++) {
#pragma unroll
        for (int j = 0; j < 4; j++) {
            int r0 = bM + warpM * 64 + i * 16 + gid;
            int c0 = bN + warpN * 32 + j * 8 + tid * 2;
#pragma unroll
            for (int e = 0; e < 4; e++) {
                int row = r0 + (e >> 1) * 8;
                int col = c0 + (e & 1);
                out[row * 256 + col] = acc[i][j][e] + b_o[col];
            }
        }
    }
}

// ---------------------------------------------------------------------------
extern "C" void kernel_launch(void* const* d_in, const int* in_sizes, int n_in,
                              void* d_out, int out_size) {
    const float* q    = (const float*)d_in[0];
    const float* kv   = (const float*)d_in[1];
    const float* bias = (const float*)d_in[2];
    const float* mask = (const float*)d_in[3];
    const float* w_q  = (const float*)d_in[4];
    const float* w_k  = (const float*)d_in[5];
    const float* w_v  = (const float*)d_in[6];
    const float* w_g  = (const float*)d_in[7];
    const float* b_g  = (const float*)d_in[8];
    const float* w_o  = (const float*)d_in[9];
    const float* b_o  = (const float*)d_in[10];
    float* out = (float*)d_out;

    bias_transpose_kernel<<<(H_DIM * R_DIM * R_DIM + 255) / 256, 256>>>(bias);

    proj_mma_kernel<<<dim3(SR_DIM / 128, HD_DIM / 128, 4), 256>>>(
        q, kv, w_q, w_k, w_v, w_g, b_g);

    const int ATTN_SMEM = ATTN_SMEM_WORDS * 4;   // 140800 B
    cudaFuncSetAttribute(attn_mma_kernel,
                         cudaFuncAttributeMaxDynamicSharedMemorySize, ATTN_SMEM);
    attn_mma_kernel<<<dim3(S_DIM, H_DIM), 256, ATTN_SMEM>>>(mask);

    outproj_mma_kernel<<<dim3(SR_DIM / 128, C_DIM / 128), 256>>>(w_o, b_o, out);
}

// round 7
// speedup vs baseline: 2.9069x; 1.1798x over previous
#include <cuda_runtime.h>
#include <math.h>
#include <stdint.h>

#define S_DIM 128
#define R_DIM 256
#define C_DIM 256
#define H_DIM 8
#define D_DIM 32
#define HD_DIM 256
#define SR_DIM (S_DIM * R_DIM)

// Scratch (device globals; allocation-free contract)
__device__ float g_Q[S_DIM * H_DIM * R_DIM * D_DIM];   // [s][h][r][d]
__device__ float g_K[S_DIM * H_DIM * R_DIM * D_DIM];
__device__ float g_V[S_DIM * H_DIM * R_DIM * D_DIM];
__device__ float g_G[S_DIM * H_DIM * R_DIM * D_DIM];
__device__ float g_O[S_DIM * H_DIM * R_DIM * D_DIM];   // gated: O * G
__device__ float g_biasT[H_DIM * R_DIM * R_DIM];       // [h][q][k]

// ---------------------------------------------------------------------------
// helpers
// ---------------------------------------------------------------------------
__device__ __forceinline__ uint32_t f2tf(float f) {
    uint32_t u;
    asm("cvt.rna.tf32.f32 %0, %1;" : "=r"(u) : "f"(f));
    return u;
}

__device__ __forceinline__ void mma_tf32(float c[4],
                                         uint32_t a0, uint32_t a1,
                                         uint32_t a2, uint32_t a3,
                                         uint32_t b0, uint32_t b1) {
    asm volatile(
        "mma.sync.aligned.m16n8k8.row.col.f32.tf32.tf32.f32 "
        "{%0,%1,%2,%3}, {%4,%5,%6,%7}, {%8,%9}, {%0,%1,%2,%3};"
        : "+f"(c[0]), "+f"(c[1]), "+f"(c[2]), "+f"(c[3])
        : "r"(a0), "r"(a1), "r"(a2), "r"(a3), "r"(b0), "r"(b1));
}

__device__ __forceinline__ void cp16(uint32_t smem_addr, const void* gptr) {
    asm volatile("cp.async.cg.shared.global [%0], [%1], 16;"
                 :: "r"(smem_addr), "l"(gptr));
}
__device__ __forceinline__ void cp_commit() {
    asm volatile("cp.async.commit_group;");
}
template <int N>
__device__ __forceinline__ void cp_wait() {
    asm volatile("cp.async.wait_group %0;" :: "n"(N));
}

// SMEM word strides for the GEMM tiles (padded, conflict-free)
#define AS_STRIDE 36
#define BS_STRIDE 132
#define AS_WORDS (128 * AS_STRIDE)   // 4608
#define BS_WORDS (32 * BS_STRIDE)    // 4224
#define GEMM_SMEM_BYTES ((2 * AS_WORDS + 2 * BS_WORDS) * 4)  // 70656

// ---------------------------------------------------------------------------
// Kernel 1: bias [q][k][h] -> biasT [h][q][k]
// ---------------------------------------------------------------------------
__global__ void bias_transpose_kernel(const float* __restrict__ bias) {
    int idx = blockIdx.x * blockDim.x + threadIdx.x;
    if (idx < H_DIM * R_DIM * R_DIM) {
        int k  = idx & 255;
        int qq = (idx >> 8) & 255;
        int h  = idx >> 16;
        g_biasT[idx] = bias[((qq << 8) + k) * 8 + h];
    }
}

// ---------------------------------------------------------------------------
// Kernel 2: fused projections, cp.async double-buffered tf32 MMA.
// C[M=32768,N=256] = A[M,256] * W[256,256]; z: 0=Q(*norm) 1=K 2=V 3=G(sigmoid)
// Raw fp32 staged in SMEM; HMMA truncates to tf32 in hardware.
// ---------------------------------------------------------------------------
__global__ void __launch_bounds__(256)
proj_mma_kernel(const float* __restrict__ qin,
                const float* __restrict__ kvin,
                const float* __restrict__ w_q,
                const float* __restrict__ w_k,
                const float* __restrict__ w_v,
                const float* __restrict__ w_g,
                const float* __restrict__ b_g) {
    extern __shared__ uint32_t smem[];
    uint32_t* Asm = smem;                    // 2 x [128][36]
    uint32_t* Bsm = smem + 2 * AS_WORDS;     // 2 x [32][132]

    int type = blockIdx.z;
    const float* A = (type == 1 || type == 2) ? kvin : qin;
    const float* W = (type == 0) ? w_q : (type == 1) ? w_k
                   : (type == 2) ? w_v : w_g;
    float* Out = (type == 0) ? g_Q : (type == 1) ? g_K
               : (type == 2) ? g_V : g_G;

    int t = threadIdx.x;
    int bM = blockIdx.x * 128;
    int bN = blockIdx.y * 128;
    int lane = t & 31, w = t >> 5;
    int warpM = w >> 2, warpN = w & 3;
    int gid = lane >> 2, tid = lane & 3;

    uint32_t asBase = (uint32_t)__cvta_generic_to_shared(Asm);
    uint32_t bsBase = (uint32_t)__cvta_generic_to_shared(Bsm);

    auto issue = [&](int kt, int buf) {
        int kc = kt * 32;
#pragma unroll
        for (int p = 0; p < 4; p++) {
            int idx = t + p * 256;
            int row = idx >> 3, c4 = (idx & 7) * 4;
            cp16(asBase + (buf * AS_WORDS + row * AS_STRIDE + c4) * 4,
                 A + (bM + row) * 256 + kc + c4);
            int br = idx >> 5, bc = (idx & 31) * 4;
            cp16(bsBase + (buf * BS_WORDS + br * BS_STRIDE + bc) * 4,
                 W + (kc + br) * 256 + bN + bc);
        }
        cp_commit();
    };

    float acc[4][4][4];
#pragma unroll
    for (int i = 0; i < 4; i++)
#pragma unroll
        for (int j = 0; j < 4; j++)
#pragma unroll
            for (int r = 0; r < 4; r++) acc[i][j][r] = 0.f;

    issue(0, 0);

    for (int kt = 0; kt < 8; kt++) {
        int cur = kt & 1;
        if (kt < 7) { issue(kt + 1, cur ^ 1); cp_wait<1>(); }
        else        { cp_wait<0>(); }
        __syncthreads();

        const uint32_t* As = Asm + cur * AS_WORDS;
        const uint32_t* Bs = Bsm + cur * BS_WORDS;
#pragma unroll
        for (int ks = 0; ks < 4; ks++) {
            int kk = ks * 8;
            uint32_t af[4][4], bf[4][2];
#pragma unroll
            for (int i = 0; i < 4; i++) {
                int r0 = warpM * 64 + i * 16;
                af[i][0] = As[(r0 + gid) * AS_STRIDE + kk + tid];
                af[i][1] = As[(r0 + gid + 8) * AS_STRIDE + kk + tid];
                af[i][2] = As[(r0 + gid) * AS_STRIDE + kk + tid + 4];
                af[i][3] = As[(r0 + gid + 8) * AS_STRIDE + kk + tid + 4];
            }
#pragma unroll
            for (int j = 0; j < 4; j++) {
                int c0 = warpN * 32 + j * 8 + gid;
                bf[j][0] = Bs[(kk + tid) * BS_STRIDE + c0];
                bf[j][1] = Bs[(kk + tid + 4) * BS_STRIDE + c0];
            }
#pragma unroll
            for (int i = 0; i < 4; i++)
#pragma unroll
                for (int j = 0; j < 4; j++)
                    mma_tf32(acc[i][j], af[i][0], af[i][1], af[i][2], af[i][3],
                             bf[j][0], bf[j][1]);
        }
        __syncthreads();
    }

    float norm = 0.17677669529663687f;  // 1/sqrt(32)
#pragma unroll
    for (int i = 0; i < 4; i++) {
#pragma unroll
        for (int j = 0; j < 4; j++) {
            int r0 = bM + warpM * 64 + i * 16 + gid;
            int c0 = bN + warpN * 32 + j * 8 + tid * 2;
#pragma unroll
            for (int e = 0; e < 4; e++) {
                int row = r0 + (e >> 1) * 8;
                int col = c0 + (e & 1);
                float v = acc[i][j][e];
                if (type == 0) v *= norm;
                if (type == 3) v = 1.f / (1.f + __expf(-(v + b_g[col])));
                int s = row >> 8, rr = row & 255;
                int h = col >> 5, d = col & 31;
                Out[((s * 8 + h) * 256 + rr) * 32 + d] = v;
            }
        }
    }
}

// ---------------------------------------------------------------------------
// Kernel 3: tensor-core attention (as R6) + fused G gating on output.
// ---------------------------------------------------------------------------
#define ATTN_SMEM_WORDS (9216 + 8320 + 17408 + 256)   // Ks + Vt + Ps + Mb

__global__ void __launch_bounds__(256)
attn_mma_kernel(const float* __restrict__ bias_mask) {
    extern __shared__ uint32_t sm[];
    uint32_t* Ks = sm;                 // [256][36] tf32 K (key, d)
    uint32_t* Vt = sm + 9216;          // [32][260] tf32 V^T (d, key)
    uint32_t* Ps = sm + 17536;         // 8 warps x [32][68] tf32 P
    float*    Mb = (float*)(sm + 34944);  // [256] mask bias

    int s = blockIdx.x, h = blockIdx.y;
    int t = threadIdx.x, lane = t & 31, w = t >> 5;
    int gid = lane >> 2, tid = lane & 3;

    const float* Qg = g_Q + (s * 8 + h) * 8192;
    const float* Kg = g_K + (s * 8 + h) * 8192;
    const float* Vg = g_V + (s * 8 + h) * 8192;
    const float* Gg = g_G + (s * 8 + h) * 8192;

    // ---- stage Q (tf32) into Ps region temporarily: Qs[256][36]
    uint32_t* Qs = Ps;
#pragma unroll
    for (int i = t; i < 2048; i += 256) {
        float4 v = ((const float4*)Qg)[i];
        int r = i >> 3, d = (i & 7) * 4;
        Qs[r * 36 + d + 0] = f2tf(v.x);
        Qs[r * 36 + d + 1] = f2tf(v.y);
        Qs[r * 36 + d + 2] = f2tf(v.z);
        Qs[r * 36 + d + 3] = f2tf(v.w);
    }
    __syncthreads();

    uint32_t qf[2][4][4];
#pragma unroll
    for (int i2 = 0; i2 < 2; i2++) {
        int r0 = w * 32 + i2 * 16;
#pragma unroll
        for (int ks = 0; ks < 4; ks++) {
            int kk = ks * 8;
            qf[i2][ks][0] = Qs[(r0 + gid) * 36 + kk + tid];
            qf[i2][ks][1] = Qs[(r0 + gid + 8) * 36 + kk + tid];
            qf[i2][ks][2] = Qs[(r0 + gid) * 36 + kk + tid + 4];
            qf[i2][ks][3] = Qs[(r0 + gid + 8) * 36 + kk + tid + 4];
        }
    }
    __syncthreads();

#pragma unroll
    for (int i = t; i < 2048; i += 256) {
        int r = i >> 3, d = (i & 7) * 4;
        float4 kv = ((const float4*)Kg)[i];
        Ks[r * 36 + d + 0] = f2tf(kv.x);
        Ks[r * 36 + d + 1] = f2tf(kv.y);
        Ks[r * 36 + d + 2] = f2tf(kv.z);
        Ks[r * 36 + d + 3] = f2tf(kv.w);
        float4 vv = ((const float4*)Vg)[i];
        Vt[(d + 0) * 260 + r] = f2tf(vv.x);
        Vt[(d + 1) * 260 + r] = f2tf(vv.y);
        Vt[(d + 2) * 260 + r] = f2tf(vv.z);
        Vt[(d + 3) * 260 + r] = f2tf(vv.w);
    }
    Mb[t] = (bias_mask[s * 256 + t] - 1.f) * 1e9f;
    __syncthreads();

    const float* biasBase = g_biasT + h * 65536;
    uint32_t* Pw = Ps + w * 2176;   // per-warp private P tile [32][68]

    float oacc[2][4][4];
#pragma unroll
    for (int i2 = 0; i2 < 2; i2++)
#pragma unroll
        for (int j2 = 0; j2 < 4; j2++)
#pragma unroll
            for (int e = 0; e < 4; e++) oacc[i2][j2][e] = 0.f;
    float rs[2][2] = {{0.f, 0.f}, {0.f, 0.f}};

    for (int kc = 0; kc < 256; kc += 64) {
        float sacc[2][8][4];
#pragma unroll
        for (int i2 = 0; i2 < 2; i2++)
#pragma unroll
            for (int j = 0; j < 8; j++)
#pragma unroll
                for (int e = 0; e < 4; e++) sacc[i2][j][e] = 0.f;

#pragma unroll
        for (int ks = 0; ks < 4; ks++) {
            int kk = ks * 8;
            uint32_t bf[8][2];
#pragma unroll
            for (int j = 0; j < 8; j++) {
                int n = kc + j * 8 + gid;
                bf[j][0] = Ks[n * 36 + kk + tid];
                bf[j][1] = Ks[n * 36 + kk + tid + 4];
            }
#pragma unroll
            for (int i2 = 0; i2 < 2; i2++)
#pragma unroll
                for (int j = 0; j < 8; j++)
                    mma_tf32(sacc[i2][j], qf[i2][ks][0], qf[i2][ks][1],
                             qf[i2][ks][2], qf[i2][ks][3], bf[j][0], bf[j][1]);
        }

#pragma unroll
        for (int i2 = 0; i2 < 2; i2++) {
            int qrow = w * 32 + i2 * 16 + gid;
#pragma unroll
            for (int j = 0; j < 8; j++) {
                int col = kc + j * 8 + tid * 2;
                float2 b0 = *(const float2*)(biasBase + qrow * 256 + col);
                float2 b1 = *(const float2*)(biasBase + (qrow + 8) * 256 + col);
                float m0 = Mb[col], m1 = Mb[col + 1];
                float p0 = __expf(sacc[i2][j][0] + b0.x + m0);
                float p1 = __expf(sacc[i2][j][1] + b0.y + m1);
                float p2 = __expf(sacc[i2][j][2] + b1.x + m0);
                float p3 = __expf(sacc[i2][j][3] + b1.y + m1);
                rs[i2][0] += p0 + p1;
                rs[i2][1] += p2 + p3;
                int lr = i2 * 16 + gid, lc = j * 8 + tid * 2;
                Pw[lr * 68 + lc]           = f2tf(p0);
                Pw[lr * 68 + lc + 1]       = f2tf(p1);
                Pw[(lr + 8) * 68 + lc]     = f2tf(p2);
                Pw[(lr + 8) * 68 + lc + 1] = f2tf(p3);
            }
        }
        __syncwarp();

#pragma unroll
        for (int ks2 = 0; ks2 < 8; ks2++) {
            int kk = ks2 * 8;
            uint32_t pf[2][4];
#pragma unroll
            for (int i2 = 0; i2 < 2; i2++) {
                int lr = i2 * 16 + gid;
                pf[i2][0] = Pw[lr * 68 + kk + tid];
                pf[i2][1] = Pw[(lr + 8) * 68 + kk + tid];
                pf[i2][2] = Pw[lr * 68 + kk + tid + 4];
                pf[i2][3] = Pw[(lr + 8) * 68 + kk + tid + 4];
            }
            uint32_t vf[4][2];
#pragma unroll
            for (int j2 = 0; j2 < 4; j2++) {
                int d = j2 * 8 + gid;
                vf[j2][0] = Vt[d * 260 + kc + kk + tid];
                vf[j2][1] = Vt[d * 260 + kc + kk + tid + 4];
            }
#pragma unroll
            for (int i2 = 0; i2 < 2; i2++)
#pragma unroll
                for (int j2 = 0; j2 < 4; j2++)
                    mma_tf32(oacc[i2][j2], pf[i2][0], pf[i2][1],
                             pf[i2][2], pf[i2][3], vf[j2][0], vf[j2][1]);
        }
        __syncwarp();
    }

#pragma unroll
    for (int i2 = 0; i2 < 2; i2++)
#pragma unroll
        for (int rp = 0; rp < 2; rp++) {
            float v = rs[i2][rp];
            v += __shfl_xor_sync(0xffffffffu, v, 1);
            v += __shfl_xor_sync(0xffffffffu, v, 2);
            rs[i2][rp] = 1.f / v;
        }

    // ---- normalize, gate with G, write g_O = O * G
    float* Og = g_O + (s * 8 + h) * 8192;
#pragma unroll
    for (int i2 = 0; i2 < 2; i2++) {
        int r0 = w * 32 + i2 * 16 + gid;
#pragma unroll
        for (int j2 = 0; j2 < 4; j2++) {
            int c = j2 * 8 + tid * 2;
            float2 gv0 = *(const float2*)(Gg + r0 * 32 + c);
            float2 gv1 = *(const float2*)(Gg + (r0 + 8) * 32 + c);
            Og[r0 * 32 + c]           = oacc[i2][j2][0] * rs[i2][0] * gv0.x;
            Og[r0 * 32 + c + 1]       = oacc[i2][j2][1] * rs[i2][0] * gv0.y;
            Og[(r0 + 8) * 32 + c]     = oacc[i2][j2][2] * rs[i2][1] * gv1.x;
            Og[(r0 + 8) * 32 + c + 1] = oacc[i2][j2][3] * rs[i2][1] * gv1.y;
        }
    }
}

// ---------------------------------------------------------------------------
// Kernel 4: out = g_O(gated) @ Wo + b_o, cp.async double-buffered tf32 MMA.
// ---------------------------------------------------------------------------
__global__ void __launch_bounds__(256)
outproj_mma_kernel(const float* __restrict__ w_o,
                   const float* __restrict__ b_o,
                   float* __restrict__ out) {
    extern __shared__ uint32_t smem[];
    uint32_t* Asm = smem;
    uint32_t* Bsm = smem + 2 * AS_WORDS;

    int t = threadIdx.x;
    int bM = blockIdx.x * 128;
    int bN = blockIdx.y * 128;
    int lane = t & 31, w = t >> 5;
    int warpM = w >> 2, warpN = w & 3;
    int gid = lane >> 2, tid = lane & 3;

    uint32_t asBase = (uint32_t)__cvta_generic_to_shared(Asm);
    uint32_t bsBase = (uint32_t)__cvta_generic_to_shared(Bsm);

    auto issue = [&](int kt, int buf) {
        int kc = kt * 32;
        int h = kc >> 5;
#pragma unroll
        for (int p = 0; p < 4; p++) {
            int idx = t + p * 256;
            int row = idx >> 3, c4 = (idx & 7) * 4;
            int m = bM + row;
            int s = m >> 8, rr = m & 255;
            cp16(asBase + (buf * AS_WORDS + row * AS_STRIDE + c4) * 4,
                 g_O + ((s * 8 + h) * 256 + rr) * 32 + c4);
            int br = idx >> 5, bc = (idx & 31) * 4;
            cp16(bsBase + (buf * BS_WORDS + br * BS_STRIDE + bc) * 4,
                 w_o + (kc + br) * 256 + bN + bc);
        }
        cp_commit();
    };

    float acc[4][4][4];
#pragma unroll
    for (int i = 0; i < 4; i++)
#pragma unroll
        for (int j = 0; j < 4; j++)
#pragma unroll
            for (int r = 0; r < 4; r++) acc[i][j][r] = 0.f;

    issue(0, 0);

    for (int kt = 0; kt < 8; kt++) {
        int cur = kt & 1;
        if (kt < 7) { issue(kt + 1, cur ^ 1); cp_wait<1>(); }
        else        { cp_wait<0>(); }
        __syncthreads();

        const uint32_t* As = Asm + cur * AS_WORDS;
        const uint32_t* Bs = Bsm + cur * BS_WORDS;
#pragma unroll
        for (int ks = 0; ks < 4; ks++) {
            int kk = ks * 8;
            uint32_t af[4][4], bf[4][2];
#pragma unroll
            for (int i = 0; i < 4; i++) {
                int r0 = warpM * 64 + i * 16;
                af[i][0] = As[(r0 + gid) * AS_STRIDE + kk + tid];
                af[i][1] = As[(r0 + gid + 8) * AS_STRIDE + kk + tid];
                af[i][2] = As[(r0 + gid) * AS_STRIDE + kk + tid + 4];
                af[i][3] = As[(r0 + gid + 8) * AS_STRIDE + kk + tid + 4];
            }
#pragma unroll
            for (int j = 0; j < 4; j++) {
                int c0 = warpN * 32 + j * 8 + gid;
                bf[j][0] = Bs[(kk + tid) * BS_STRIDE + c0];
                bf[j][1] = Bs[(kk + tid + 4) * BS_STRIDE + c0];
            }
#pragma unroll
            for (int i = 0; i < 4; i++)
#pragma unroll
                for (int j = 0; j < 4; j++)
                    mma_tf32(acc[i][j], af[i][0], af[i][1], af[i][2], af[i][3],
                             bf[j][0], bf[j][1]);
        }
        __syncthreads();
    }

#pragma unroll
    for (int i = 0; i < 4; i++) {
#pragma unroll
        for (int j = 0; j < 4; j++) {
            int r0 = bM + warpM * 64 + i * 16 + gid;
            int c0 = bN + warpN * 32 + j * 8 + tid * 2;
#pragma unroll
            for (int e = 0; e < 4; e++) {
                int row = r0 + (e >> 1) * 8;
                int col = c0 + (e & 1);
                out[row * 256 + col] = acc[i][j][e] + b_o[col];
            }
        }
    }
}

// ---------------------------------------------------------------------------
extern "C" void kernel_launch(void* const* d_in, const int* in_sizes, int n_in,
                              void* d_out, int out_size) {
    const float* q    = (const float*)d_in[0];
    const float* kv   = (const float*)d_in[1];
    const float* bias = (const float*)d_in[2];
    const float* mask = (const float*)d_in[3];
    const float* w_q  = (const float*)d_in[4];
    const float* w_k  = (const float*)d_in[5];
    const float* w_v  = (const float*)d_in[6];
    const float* w_g  = (const float*)d_in[7];
    const float* b_g  = (const float*)d_in[8];
    const float* w_o  = (const float*)d_in[9];
    const float* b_o  = (const float*)d_in[10];
    float* out = (float*)d_out;

    bias_transpose_kernel<<<(H_DIM * R_DIM * R_DIM + 255) / 256, 256>>>(bias);

    cudaFuncSetAttribute(proj_mma_kernel,
                         cudaFuncAttributeMaxDynamicSharedMemorySize,
                         GEMM_SMEM_BYTES);
    proj_mma_kernel<<<dim3(SR_DIM / 128, HD_DIM / 128, 4), 256,
                      GEMM_SMEM_BYTES>>>(q, kv, w_q, w_k, w_v, w_g, b_g);

    const int ATTN_SMEM = ATTN_SMEM_WORDS * 4;   // 140800 B
    cudaFuncSetAttribute(attn_mma_kernel,
                         cudaFuncAttributeMaxDynamicSharedMemorySize, ATTN_SMEM);
    attn_mma_kernel<<<dim3(S_DIM, H_DIM), 256, ATTN_SMEM>>>(mask);

    cudaFuncSetAttribute(outproj_mma_kernel,
                         cudaFuncAttributeMaxDynamicSharedMemorySize,
                         GEMM_SMEM_BYTES);
    outproj_mma_kernel<<<dim3(SR_DIM / 128, C_DIM / 128), 256,
                         GEMM_SMEM_BYTES>>>(w_o, b_o, out);
}